// round 9
// baseline (speedup 1.0000x reference)
#include <cuda_runtime.h>
#include <cuda_fp16.h>
#include <cstdint>

#define TOTAL_ELEMS 33554432

__device__ __align__(128) float g_acc[TOTAL_ELEMS];
__device__ __align__(128) __half g_xhi[TOTAL_ELEMS];
__device__ __align__(128) __half g_whi[3342336];

struct Dims6 { int size[6]; int stride[6]; };

// stage: A 128x144B | B 128x144B   (BK=64: 128B data + 16B pad per row)
#define APITCH 144
#define B_OFF  18432
#define STAGE_B 36864
#define NSTAGE  3
#define DYN_SMEM (NSTAGE * STAGE_B)   // 110592; 2 CTAs/SM

__device__ __forceinline__ uint32_t smem_u32(const void* p) {
    uint32_t a;
    asm("{ .reg .u64 t; cvta.to.shared.u64 t, %1; cvt.u32.u64 %0, t; }" : "=r"(a) : "l"(p));
    return a;
}
__device__ __forceinline__ void ldsm4(uint32_t* r, uint32_t a) {
    asm volatile("ldmatrix.sync.aligned.m8n8.x4.shared.b16 {%0,%1,%2,%3}, [%4];"
        : "=r"(r[0]), "=r"(r[1]), "=r"(r[2]), "=r"(r[3]) : "r"(a));
}
__device__ __forceinline__ void mma16816(float* d, const uint32_t* a, const uint32_t* b) {
    asm volatile("mma.sync.aligned.m16n8k16.row.col.f32.f16.f16.f32 "
        "{%0,%1,%2,%3}, {%4,%5,%6,%7}, {%8,%9}, {%0,%1,%2,%3};"
        : "+f"(d[0]), "+f"(d[1]), "+f"(d[2]), "+f"(d[3])
        : "r"(a[0]), "r"(a[1]), "r"(a[2]), "r"(a[3]), "r"(b[0]), "r"(b[1]));
}
__device__ __forceinline__ void cpa16(uint32_t s, const void* g) {
    asm volatile("cp.async.cg.shared.global [%0], [%1], 16;" :: "r"(s), "l"(g));
}
#define CPA_COMMIT() asm volatile("cp.async.commit_group;" ::: "memory")
#define CPA_WAITG(k) asm volatile("cp.async.wait_group %0;" :: "n"(k) : "memory")

// ================= prep: X fp32 (original) -> fp16 (permuted, c fastest) ==========
__global__ __launch_bounds__(256) void prep_x(const float* __restrict__ X)
{
    __shared__ float ts[64][65];
    const int b = blockIdx.x >> 12, sblk = blockIdx.x & 4095;
    const size_t s0 = (size_t)sblk * 64;
    const int t = threadIdx.x, sl = t & 63, ch = t >> 6;
    const float* xp = X + (size_t)b * 64 * 262144 + s0;
    #pragma unroll
    for (int i = 0; i < 16; i++) {
        const int c = ch + i * 4;
        ts[sl][c] = xp[(size_t)c * 262144 + sl];
    }
    __syncthreads();
    const int srow = t >> 2, sub = t & 3;
    const size_t row = (size_t)b * 262144 + s0 + srow;
    __half* hp = g_xhi + row * 64 + sub * 16;
    #pragma unroll
    for (int j = 0; j < 16; j++)
        hp[j] = __float2half(ts[srow][sub * 16 + j]);
}

// one launch converts all six weight matrices
__global__ __launch_bounds__(256) void prep_w_all(
    const float* __restrict__ w_d, const float* __restrict__ w_h,
    const float* __restrict__ w_w, const float* __restrict__ w_pd,
    const float* __restrict__ w_ph, const float* __restrict__ w_pw)
{
    const int b = blockIdx.x;
    const float* W; int woff, n, row;
    if (b < 3072) {
        const int op = b >> 10; row = b & 1023; n = 1024; woff = op * 1048576;
        W = (op == 0) ? w_d : (op == 1) ? w_h : w_w;
    } else {
        const int t = b - 3072;
        const int op = t >> 8; row = t & 255; n = 256; woff = 3145728 + op * 65536;
        W = (op == 0) ? w_pd : (op == 1) ? w_ph : w_pw;
    }
    const float* wp = W + (size_t)row * n;
    __half* hp = g_whi + woff + (size_t)row * n;
    for (int c = threadIdx.x; c < n; c += 256)
        hp[c] = __float2half(wp[c]);
}

// ==== GEMM: 128m x 128n tile, BK=64, 256 threads, 3-stage cp.async, 2 CTA/SM ====
__global__ __launch_bounds__(256, 2)
void axial_mma(int woff, const float* __restrict__ Bias, Dims6 dims,
               int n, int str_sp, int first)
{
    extern __shared__ __align__(16) char dsm[];
    __shared__ int base_s[128];

    const int tid = threadIdx.x;
    const int lane = tid & 31, wid = tid >> 5;
    const int nb = blockIdx.x, bx = blockIdx.y;
    const int wm = wid & 3, wn = wid >> 2;     // warp tile: 32m x 64n

    if (tid < 128) {
        int m = bx * 128 + tid;
        int off = 0;
        #pragma unroll
        for (int j = 0; j < 6; j++) { off += (m % dims.size[j]) * dims.stride[j]; m /= dims.size[j]; }
        base_s[tid] = off;
    }
    __syncthreads();

    const uint32_t sb = smem_u32(dsm);

    // ---- cp.async mapping: thread t -> row t>>1, 64B half = (t&1)*64 ----
    const int row = tid >> 1;
    const int half = (tid & 1) * 64;
    const int aBase = base_s[row];
    const char* aP = (const char*)g_xhi;
    const char* bP = (const char*)(g_whi + woff) + ((size_t)(nb * 128 + row)) * n * 2 + half;
    const uint32_t rSm = (uint32_t)(row * APITCH + half);

    auto issue = [&](int ck) {
        const uint32_t st = sb + (uint32_t)((ck % 3) * STAGE_B);
        const size_t aoff = ((size_t)(aBase + ck * str_sp)) * 128 + half;
        cpa16(st + rSm,      aP + aoff);
        cpa16(st + rSm + 16, aP + aoff + 16);
        cpa16(st + rSm + 32, aP + aoff + 32);
        cpa16(st + rSm + 48, aP + aoff + 48);
        const size_t boff = (size_t)ck * 128;
        cpa16(st + B_OFF + rSm,      bP + boff);
        cpa16(st + B_OFF + rSm + 16, bP + boff + 16);
        cpa16(st + B_OFF + rSm + 32, bP + boff + 32);
        cpa16(st + B_OFF + rSm + 48, bP + boff + 48);
    };

    // ---- ldsm lane offsets ----
    const uint32_t a_lm = (uint32_t)((wm * 32 + (lane & 15)) * APITCH + (lane >> 4) * 16);
    const uint32_t b_lm = (uint32_t)(B_OFF
        + (wn * 64 + ((lane >> 4) & 1) * 8 + (lane & 7)) * APITCH + ((lane >> 3) & 1) * 16);

    float acc[2][8][4];
    #pragma unroll
    for (int i = 0; i < 2; i++)
        #pragma unroll
        for (int j = 0; j < 8; j++)
            #pragma unroll
            for (int q = 0; q < 4; q++) acc[i][j][q] = 0.f;

    const int nk = n >> 6;
    issue(0); CPA_COMMIT();
    issue(1); CPA_COMMIT();

    for (int ck = 0; ck < nk; ck++) {
        if (ck + 1 < nk) CPA_WAITG(1); else CPA_WAITG(0);
        __syncthreads();
        if (ck + 2 < nk) { issue(ck + 2); CPA_COMMIT(); }

        const uint32_t st = sb + (uint32_t)((ck % 3) * STAGE_B);
        #pragma unroll
        for (int ks = 0; ks < 4; ks++) {
            const uint32_t ko = (uint32_t)(ks * 32);
            uint32_t ah[2][4], br[4];
            ldsm4(ah[0], st + a_lm + ko);
            ldsm4(ah[1], st + a_lm + 16 * APITCH + ko);
            #pragma unroll
            for (int ntp = 0; ntp < 4; ntp++) {
                ldsm4(br, st + b_lm + ntp * 16 * APITCH + ko);
                mma16816(acc[0][2*ntp],   ah[0], br);
                mma16816(acc[0][2*ntp+1], ah[0], br + 2);
                mma16816(acc[1][2*ntp],   ah[1], br);
                mma16816(acc[1][2*ntp+1], ah[1], br + 2);
            }
        }
    }

    // ---- epilogue: RMW into permuted g_acc (c contiguous -> float2) ----
    {
        const int s_out = nb * 2 + wn;
        const int r0 = lane >> 2, cp = (lane & 3) * 2;
        #pragma unroll
        for (int mt = 0; mt < 2; mt++) {
            const int ml = wm * 32 + mt * 16 + r0;
            const size_t row0 = (size_t)(base_s[ml]     + s_out * str_sp);
            const size_t row1 = (size_t)(base_s[ml + 8] + s_out * str_sp);
            #pragma unroll
            for (int nt = 0; nt < 8; nt++) {
                const int o = nb * 128 + wn * 64 + nt * 8 + cp;
                const int c_out = nt * 8 + cp;
                const float2 bv = __ldg((const float2*)(Bias + o));
                float2* g0 = (float2*)(g_acc + row0 * 64 + c_out);
                float2* g1 = (float2*)(g_acc + row1 * 64 + c_out);
                if (first) {
                    *g0 = make_float2(acc[mt][nt][0] + bv.x, acc[mt][nt][1] + bv.y);
                    *g1 = make_float2(acc[mt][nt][2] + bv.x, acc[mt][nt][3] + bv.y);
                } else {
                    float2 v0 = *g0, v1 = *g1;
                    v0.x += acc[mt][nt][0] + bv.x; v0.y += acc[mt][nt][1] + bv.y;
                    v1.x += acc[mt][nt][2] + bv.x; v1.y += acc[mt][nt][3] + bv.y;
                    *g0 = v0; *g1 = v1;
                }
            }
        }
    }
}

// ============ finalize: permuted g_acc -> leaky + residual -> original-layout out =======
__global__ __launch_bounds__(256) void finalize2(const float* __restrict__ X,
                                                 float* __restrict__ Y)
{
    __shared__ float ts[64][65];
    const int b = blockIdx.x >> 12, sblk = blockIdx.x & 4095;
    const size_t s0 = (size_t)sblk * 64;
    const int t = threadIdx.x, sl = t & 63, ch = t >> 6;
    #pragma unroll
    for (int i = 0; i < 16; i++) {
        const int s = ch + i * 4;
        ts[s][sl] = g_acc[((size_t)b * 262144 + s0 + s) * 64 + sl];
    }
    __syncthreads();
    #pragma unroll
    for (int i = 0; i < 16; i++) {
        const int c = ch + i * 4;
        const size_t oa = ((size_t)(b * 64 + c)) * 262144 + s0 + sl;
        const float a = ts[sl][c];
        Y[oa] = X[oa] + (a > 0.f ? a : 0.01f * a);
    }
}

extern "C" void kernel_launch(void* const* d_in, const int* in_sizes, int n_in,
                              void* d_out, int out_size)
{
    const float* x    = (const float*)d_in[0];
    const float* w_d  = (const float*)d_in[1];
    const float* b_d  = (const float*)d_in[2];
    const float* w_h  = (const float*)d_in[3];
    const float* b_h  = (const float*)d_in[4];
    const float* w_w  = (const float*)d_in[5];
    const float* b_w  = (const float*)d_in[6];
    const float* w_pd = (const float*)d_in[7];
    const float* b_pd = (const float*)d_in[8];
    const float* w_ph = (const float*)d_in[9];
    const float* b_ph = (const float*)d_in[10];
    const float* w_pw = (const float*)d_in[11];
    const float* b_pw = (const float*)d_in[12];

    cudaFuncSetAttribute(axial_mma, cudaFuncAttributeMaxDynamicSharedMemorySize, DYN_SMEM);

    prep_x<<<8192, 256>>>(x);
    prep_w_all<<<3840, 256>>>(w_d, w_h, w_w, w_pd, w_ph, w_pw);

    // m-dims (sizes, spatial-row strides incl. b=262144), fastest first
    Dims6 dD = {{4,4,4,16,16,2},  {1,4,16,64,1024,262144}};    // axis d (str 16384)
    Dims6 dH = {{4,4,4,16,16,2},  {1,4,16,64,16384,262144}};   // axis h (str 1024)
    Dims6 dW = {{4,4,4,16,16,2},  {1,4,16,1024,16384,262144}}; // axis w (str 64)
    Dims6 dP = {{4,4,16,16,16,2}, {1,4,64,1024,16384,262144}}; // axis p (str 16)
    Dims6 dQ = {{4,4,16,16,16,2}, {1,16,64,1024,16384,262144}};// axis q (str 4)
    Dims6 dR = {{4,4,16,16,16,2}, {4,16,64,1024,16384,262144}};// axis r (str 1)

    // launches 2-4: patch ops; launch 5 (ncu -s 5 target): image op d
    axial_mma<<<dim3(2, 1024), 256, DYN_SMEM>>>(3145728, b_pd, dP, 256, 16,    1);
    axial_mma<<<dim3(2, 1024), 256, DYN_SMEM>>>(3211264, b_ph, dQ, 256, 4,     0);
    axial_mma<<<dim3(2, 1024), 256, DYN_SMEM>>>(3276800, b_pw, dR, 256, 1,     0);
    axial_mma<<<dim3(8, 256),  256, DYN_SMEM>>>(0,       b_d,  dD, 1024, 16384, 0);
    axial_mma<<<dim3(8, 256),  256, DYN_SMEM>>>(1048576, b_h,  dH, 1024, 1024,  0);
    axial_mma<<<dim3(8, 256),  256, DYN_SMEM>>>(2097152, b_w,  dW, 1024, 64,    0);

    finalize2<<<8192, 256>>>(x, (float*)d_out);
}

// round 10
// speedup vs baseline: 1.0547x; 1.0547x over previous
#include <cuda_runtime.h>
#include <cuda_fp16.h>
#include <cstdint>

#define TOTAL_ELEMS 33554432

__device__ __align__(128) float g_acc[TOTAL_ELEMS];
__device__ __align__(128) __half g_xhi[TOTAL_ELEMS];
__device__ __align__(128) __half g_whi[3342336];

struct Dims6 { int size[6]; int stride[6]; };

// ---- image GEMM stage: A 128x144B | B 128x144B (BK=64) ----
#define APITCH 144
#define B_OFF  18432
#define STAGE_B 36864
#define DYN_SMEM (3 * STAGE_B)      // 110592; 2 CTAs/SM

// ---- patch_fused stage: A 256x80B | B 64x80B (BK=32) ----
#define PF_ASZ  20480
#define PF_BOFF PF_ASZ
#define PF_STG  25600
#define PF_DYN  (4 * PF_STG)        // 102400; 2 CTAs/SM

__device__ __forceinline__ uint32_t smem_u32(const void* p) {
    uint32_t a;
    asm("{ .reg .u64 t; cvta.to.shared.u64 t, %1; cvt.u32.u64 %0, t; }" : "=r"(a) : "l"(p));
    return a;
}
__device__ __forceinline__ void ldsm4(uint32_t* r, uint32_t a) {
    asm volatile("ldmatrix.sync.aligned.m8n8.x4.shared.b16 {%0,%1,%2,%3}, [%4];"
        : "=r"(r[0]), "=r"(r[1]), "=r"(r[2]), "=r"(r[3]) : "r"(a));
}
__device__ __forceinline__ void mma16816(float* d, const uint32_t* a, const uint32_t* b) {
    asm volatile("mma.sync.aligned.m16n8k16.row.col.f32.f16.f16.f32 "
        "{%0,%1,%2,%3}, {%4,%5,%6,%7}, {%8,%9}, {%0,%1,%2,%3};"
        : "+f"(d[0]), "+f"(d[1]), "+f"(d[2]), "+f"(d[3])
        : "r"(a[0]), "r"(a[1]), "r"(a[2]), "r"(a[3]), "r"(b[0]), "r"(b[1]));
}
__device__ __forceinline__ void cpa16(uint32_t s, const void* g) {
    asm volatile("cp.async.cg.shared.global [%0], [%1], 16;" :: "r"(s), "l"(g));
}
#define CPA_COMMIT() asm volatile("cp.async.commit_group;" ::: "memory")
#define CPA_WAITG(k) asm volatile("cp.async.wait_group %0;" :: "n"(k) : "memory")

// ================= prep: X fp32 (original) -> fp16 (permuted, c fastest) ==========
__global__ __launch_bounds__(256) void prep_x(const float* __restrict__ X)
{
    __shared__ float ts[64][65];
    const int b = blockIdx.x >> 12, sblk = blockIdx.x & 4095;
    const size_t s0 = (size_t)sblk * 64;
    const int t = threadIdx.x, sl = t & 63, ch = t >> 6;
    const float* xp = X + (size_t)b * 64 * 262144 + s0;
    #pragma unroll
    for (int i = 0; i < 16; i++) {
        const int c = ch + i * 4;
        ts[sl][c] = xp[(size_t)c * 262144 + sl];
    }
    __syncthreads();
    const int srow = t >> 2, sub = t & 3;
    const size_t row = (size_t)b * 262144 + s0 + srow;
    __half* hp = g_xhi + row * 64 + sub * 16;
    #pragma unroll
    for (int j = 0; j < 16; j++)
        hp[j] = __float2half(ts[srow][sub * 16 + j]);
}

__global__ __launch_bounds__(256) void prep_w_all(
    const float* __restrict__ w_d, const float* __restrict__ w_h,
    const float* __restrict__ w_w, const float* __restrict__ w_pd,
    const float* __restrict__ w_ph, const float* __restrict__ w_pw)
{
    const int b = blockIdx.x;
    const float* W; int woff, n, row;
    if (b < 3072) {
        const int op = b >> 10; row = b & 1023; n = 1024; woff = op * 1048576;
        W = (op == 0) ? w_d : (op == 1) ? w_h : w_w;
    } else {
        const int t = b - 3072;
        const int op = t >> 8; row = t & 255; n = 256; woff = 3145728 + op * 65536;
        W = (op == 0) ? w_pd : (op == 1) ? w_ph : w_pw;
    }
    const float* wp = W + (size_t)row * n;
    __half* hp = g_whi + woff + (size_t)row * n;
    for (int c = threadIdx.x; c < n; c += 256)
        hp[c] = __float2half(wp[c]);
}

// ========== patch_fused: 3 patch ops in one kernel. Tile M=256 x N=64, K=768 ==========
// CTA: fixed output (p,q,r) = blockIdx.x, j2 = blockIdx.y (128 dhw rows x 2 b).
// Single write to g_acc (no RMW).
__global__ __launch_bounds__(256, 2)
void patch_fused(const float* __restrict__ b_pd, const float* __restrict__ b_ph,
                 const float* __restrict__ b_pw)
{
    extern __shared__ __align__(16) char dsm[];
    __shared__ int base_in[256];
    __shared__ float bias_s[64];
    __shared__ int c0_s[3], step_s[3];
    __shared__ long wb_s[3];

    const int tid = threadIdx.x, lane = tid & 31, wid = tid >> 5;
    const int pqr = blockIdx.x, j2 = blockIdx.y;
    const int p = pqr >> 4, q = (pqr >> 2) & 3, r = pqr & 3;

    base_in[tid] = (tid >> 7) * 262144 + (j2 * 128 + (tid & 127)) * 64;
    if (tid < 64)
        bias_s[tid] = __ldg(b_pd + p * 64 + tid) + __ldg(b_ph + q * 64 + tid)
                    + __ldg(b_pw + r * 64 + tid);
    if (tid == 0) {
        c0_s[0] = q * 4 + r;      step_s[0] = 16;
        c0_s[1] = p * 16 + r;     step_s[1] = 4;
        c0_s[2] = p * 16 + q * 4; step_s[2] = 1;
        wb_s[0] = (long)(3145728 + p * 16384) * 2;
        wb_s[1] = (long)(3211264 + q * 16384) * 2;
        wb_s[2] = (long)(3276800 + r * 16384) * 2;
    }
    __syncthreads();

    const uint32_t sb = smem_u32(dsm);
    const int myrow = base_in[tid];
    const uint32_t aSm = (uint32_t)(tid * 80);
    const uint32_t bSm = (uint32_t)(PF_BOFF + (tid >> 2) * 80 + (tid & 3) * 16);
    const long bRow = (long)(tid >> 2) * 512 + (tid & 3) * 16;

    auto issue = [&](int ck) {
        const int op = ck >> 3, s32 = ck & 7, s = s32 >> 1, half = s32 & 1;
        const uint32_t st = sb + (uint32_t)((ck & 3) * PF_STG);
        const char* ga = (const char*)g_xhi
            + ((size_t)(myrow + c0_s[op] + s * step_s[op])) * 128 + half * 64;
        cpa16(st + aSm,      ga);
        cpa16(st + aSm + 16, ga + 16);
        cpa16(st + aSm + 32, ga + 32);
        cpa16(st + aSm + 48, ga + 48);
        const char* gb = (const char*)g_whi + wb_s[op] + bRow + s * 128 + half * 64;
        cpa16(st + bSm, gb);
    };

    const uint32_t a_lm = (uint32_t)((wid * 32 + (lane & 15)) * 80 + (lane >> 4) * 16);
    const uint32_t b_lm = (uint32_t)(PF_BOFF
        + (((lane >> 4) & 1) * 8 + (lane & 7)) * 80 + ((lane >> 3) & 1) * 16);

    float acc[2][8][4];
    #pragma unroll
    for (int i = 0; i < 2; i++)
        #pragma unroll
        for (int j = 0; j < 8; j++)
            #pragma unroll
            for (int u = 0; u < 4; u++) acc[i][j][u] = 0.f;

    issue(0); CPA_COMMIT();
    issue(1); CPA_COMMIT();
    issue(2); CPA_COMMIT();

    for (int ck = 0; ck < 24; ck++) {
        if (ck + 1 < 24) CPA_WAITG(2); else CPA_WAITG(0);
        __syncthreads();
        if (ck + 3 < 24) { issue(ck + 3); CPA_COMMIT(); }

        const uint32_t st = sb + (uint32_t)((ck & 3) * PF_STG);
        #pragma unroll
        for (int ks = 0; ks < 2; ks++) {
            const uint32_t ko = (uint32_t)(ks * 32);
            uint32_t ah[2][4], br[4];
            ldsm4(ah[0], st + a_lm + ko);
            ldsm4(ah[1], st + a_lm + 16 * 80 + ko);
            #pragma unroll
            for (int ntp = 0; ntp < 4; ntp++) {
                ldsm4(br, st + b_lm + ntp * 16 * 80 + ko);
                mma16816(acc[0][2*ntp],   ah[0], br);
                mma16816(acc[0][2*ntp+1], ah[0], br + 2);
                mma16816(acc[1][2*ntp],   ah[1], br);
                mma16816(acc[1][2*ntp+1], ah[1], br + 2);
            }
        }
    }

    // epilogue: single coalesced-ish write, rows are 256B contiguous in g_acc
    {
        const int r0 = lane >> 2, cp = (lane & 3) * 2;
        #pragma unroll
        for (int mt = 0; mt < 2; mt++) {
            const int m0 = wid * 32 + mt * 16 + r0;
            const size_t o0 = ((size_t)(base_in[m0]     + pqr)) * 64;
            const size_t o1 = ((size_t)(base_in[m0 + 8] + pqr)) * 64;
            #pragma unroll
            for (int nt = 0; nt < 8; nt++) {
                const int c = nt * 8 + cp;
                const float bx = bias_s[c], by = bias_s[c + 1];
                *(float2*)(g_acc + o0 + c) = make_float2(acc[mt][nt][0] + bx,
                                                         acc[mt][nt][1] + by);
                *(float2*)(g_acc + o1 + c) = make_float2(acc[mt][nt][2] + bx,
                                                         acc[mt][nt][3] + by);
            }
        }
    }
}

// ==== image GEMM: 128m x 128n tile, BK=64, 3-stage, 2 CTA/SM (at HMMA cap) ====
__global__ __launch_bounds__(256, 2)
void axial_mma(int woff, const float* __restrict__ Bias, Dims6 dims,
               int n, int str_sp)
{
    extern __shared__ __align__(16) char dsm[];
    __shared__ int base_s[128];

    const int tid = threadIdx.x;
    const int lane = tid & 31, wid = tid >> 5;
    const int nb = blockIdx.x, bx = blockIdx.y;
    const int wm = wid & 3, wn = wid >> 2;

    if (tid < 128) {
        int m = bx * 128 + tid;
        int off = 0;
        #pragma unroll
        for (int j = 0; j < 6; j++) { off += (m % dims.size[j]) * dims.stride[j]; m /= dims.size[j]; }
        base_s[tid] = off;
    }
    __syncthreads();

    const uint32_t sb = smem_u32(dsm);

    const int row = tid >> 1;
    const int half = (tid & 1) * 64;
    const int aBase = base_s[row];
    const char* aP = (const char*)g_xhi;
    const char* bP = (const char*)(g_whi + woff) + ((size_t)(nb * 128 + row)) * n * 2 + half;
    const uint32_t rSm = (uint32_t)(row * APITCH + half);

    auto issue = [&](int ck) {
        const uint32_t st = sb + (uint32_t)((ck % 3) * STAGE_B);
        const size_t aoff = ((size_t)(aBase + ck * str_sp)) * 128 + half;
        cpa16(st + rSm,      aP + aoff);
        cpa16(st + rSm + 16, aP + aoff + 16);
        cpa16(st + rSm + 32, aP + aoff + 32);
        cpa16(st + rSm + 48, aP + aoff + 48);
        const size_t boff = (size_t)ck * 128;
        cpa16(st + B_OFF + rSm,      bP + boff);
        cpa16(st + B_OFF + rSm + 16, bP + boff + 16);
        cpa16(st + B_OFF + rSm + 32, bP + boff + 32);
        cpa16(st + B_OFF + rSm + 48, bP + boff + 48);
    };

    const uint32_t a_lm = (uint32_t)((wm * 32 + (lane & 15)) * APITCH + (lane >> 4) * 16);
    const uint32_t b_lm = (uint32_t)(B_OFF
        + (wn * 64 + ((lane >> 4) & 1) * 8 + (lane & 7)) * APITCH + ((lane >> 3) & 1) * 16);

    float acc[2][8][4];
    #pragma unroll
    for (int i = 0; i < 2; i++)
        #pragma unroll
        for (int j = 0; j < 8; j++)
            #pragma unroll
            for (int q = 0; q < 4; q++) acc[i][j][q] = 0.f;

    const int nk = n >> 6;
    issue(0); CPA_COMMIT();
    issue(1); CPA_COMMIT();

    for (int ck = 0; ck < nk; ck++) {
        if (ck + 1 < nk) CPA_WAITG(1); else CPA_WAITG(0);
        __syncthreads();
        if (ck + 2 < nk) { issue(ck + 2); CPA_COMMIT(); }

        const uint32_t st = sb + (uint32_t)((ck % 3) * STAGE_B);
        #pragma unroll
        for (int ks = 0; ks < 4; ks++) {
            const uint32_t ko = (uint32_t)(ks * 32);
            uint32_t ah[2][4], br[4];
            ldsm4(ah[0], st + a_lm + ko);
            ldsm4(ah[1], st + a_lm + 16 * APITCH + ko);
            #pragma unroll
            for (int ntp = 0; ntp < 4; ntp++) {
                ldsm4(br, st + b_lm + ntp * 16 * APITCH + ko);
                mma16816(acc[0][2*ntp],   ah[0], br);
                mma16816(acc[0][2*ntp+1], ah[0], br + 2);
                mma16816(acc[1][2*ntp],   ah[1], br);
                mma16816(acc[1][2*ntp+1], ah[1], br + 2);
            }
        }
    }

    // epilogue: RMW into permuted g_acc
    {
        const int s_out = nb * 2 + wn;
        const int r0 = lane >> 2, cp = (lane & 3) * 2;
        #pragma unroll
        for (int mt = 0; mt < 2; mt++) {
            const int ml = wm * 32 + mt * 16 + r0;
            const size_t row0 = (size_t)(base_s[ml]     + s_out * str_sp);
            const size_t row1 = (size_t)(base_s[ml + 8] + s_out * str_sp);
            #pragma unroll
            for (int nt = 0; nt < 8; nt++) {
                const int o = nb * 128 + wn * 64 + nt * 8 + cp;
                const int c_out = nt * 8 + cp;
                const float2 bv = __ldg((const float2*)(Bias + o));
                float2* g0 = (float2*)(g_acc + row0 * 64 + c_out);
                float2* g1 = (float2*)(g_acc + row1 * 64 + c_out);
                float2 v0 = *g0, v1 = *g1;
                v0.x += acc[mt][nt][0] + bv.x; v0.y += acc[mt][nt][1] + bv.y;
                v1.x += acc[mt][nt][2] + bv.x; v1.y += acc[mt][nt][3] + bv.y;
                *g0 = v0; *g1 = v1;
            }
        }
    }
}

// ============ finalize: permuted g_acc -> leaky + residual -> original-layout out =======
__global__ __launch_bounds__(256) void finalize2(const float* __restrict__ X,
                                                 float* __restrict__ Y)
{
    __shared__ float ts[64][65];
    const int b = blockIdx.x >> 12, sblk = blockIdx.x & 4095;
    const size_t s0 = (size_t)sblk * 64;
    const int t = threadIdx.x, sl = t & 63, ch = t >> 6;
    #pragma unroll
    for (int i = 0; i < 16; i++) {
        const int s = ch + i * 4;
        ts[s][sl] = g_acc[((size_t)b * 262144 + s0 + s) * 64 + sl];
    }
    __syncthreads();
    #pragma unroll
    for (int i = 0; i < 16; i++) {
        const int c = ch + i * 4;
        const size_t oa = ((size_t)(b * 64 + c)) * 262144 + s0 + sl;
        const float a = ts[sl][c];
        Y[oa] = X[oa] + (a > 0.f ? a : 0.01f * a);
    }
}

extern "C" void kernel_launch(void* const* d_in, const int* in_sizes, int n_in,
                              void* d_out, int out_size)
{
    const float* x    = (const float*)d_in[0];
    const float* w_d  = (const float*)d_in[1];
    const float* b_d  = (const float*)d_in[2];
    const float* w_h  = (const float*)d_in[3];
    const float* b_h  = (const float*)d_in[4];
    const float* w_w  = (const float*)d_in[5];
    const float* b_w  = (const float*)d_in[6];
    const float* w_pd = (const float*)d_in[7];
    const float* b_pd = (const float*)d_in[8];
    const float* w_ph = (const float*)d_in[9];
    const float* b_ph = (const float*)d_in[10];
    const float* w_pw = (const float*)d_in[11];
    const float* b_pw = (const float*)d_in[12];

    cudaFuncSetAttribute(axial_mma,   cudaFuncAttributeMaxDynamicSharedMemorySize, DYN_SMEM);
    cudaFuncSetAttribute(patch_fused, cudaFuncAttributeMaxDynamicSharedMemorySize, PF_DYN);

    prep_x<<<8192, 256>>>(x);
    prep_w_all<<<3840, 256>>>(w_d, w_h, w_w, w_pd, w_ph, w_pw);

    // patch ops: one fused launch, writes g_acc (no RMW)
    patch_fused<<<dim3(64, 32), 256, PF_DYN>>>(b_pd, b_ph, b_pw);

    // image m-dims (sizes, spatial-row strides incl. b=262144), fastest first
    Dims6 dD = {{4,4,4,16,16,2},  {1,4,16,64,1024,262144}};    // axis d (str 16384)
    Dims6 dH = {{4,4,4,16,16,2},  {1,4,16,64,16384,262144}};   // axis h (str 1024)
    Dims6 dW = {{4,4,4,16,16,2},  {1,4,16,1024,16384,262144}}; // axis w (str 64)

    axial_mma<<<dim3(8, 256), 256, DYN_SMEM>>>(0,       b_d, dD, 1024, 16384);
    axial_mma<<<dim3(8, 256), 256, DYN_SMEM>>>(1048576, b_h, dH, 1024, 1024);
    axial_mma<<<dim3(8, 256), 256, DYN_SMEM>>>(2097152, b_w, dW, 1024, 64);

    finalize2<<<8192, 256>>>(x, (float*)d_out);
}

// round 11
// speedup vs baseline: 1.0999x; 1.0429x over previous
#include <cuda_runtime.h>
#include <cuda_fp16.h>
#include <cstdint>

#define TOTAL_ELEMS 33554432

__device__ __align__(128) float g_acc[TOTAL_ELEMS];
__device__ __align__(128) __half g_xhi[TOTAL_ELEMS];
__device__ __align__(128) __half g_whi[3342336];

// ---- image GEMM stage: A 128x144B | B 128x144B (BK=64) ----
#define APITCH 144
#define B_OFF  18432
#define STAGE_B 36864
#define DYN_SMEM (3 * STAGE_B)      // 110592; 2 CTAs/SM

// ---- patch_fused stage: A 256x80B | B 64x80B (BK=32) ----
#define PF_ASZ  20480
#define PF_BOFF PF_ASZ
#define PF_STG  25600
#define PF_DYN  (4 * PF_STG)        // 102400; 2 CTAs/SM

#define CS_PITCH 133                // fp32 staging pitch (mod-32 = 5, conflict-free columns)

__device__ __forceinline__ uint32_t smem_u32(const void* p) {
    uint32_t a;
    asm("{ .reg .u64 t; cvta.to.shared.u64 t, %1; cvt.u32.u64 %0, t; }" : "=r"(a) : "l"(p));
    return a;
}
__device__ __forceinline__ void ldsm4(uint32_t* r, uint32_t a) {
    asm volatile("ldmatrix.sync.aligned.m8n8.x4.shared.b16 {%0,%1,%2,%3}, [%4];"
        : "=r"(r[0]), "=r"(r[1]), "=r"(r[2]), "=r"(r[3]) : "r"(a));
}
__device__ __forceinline__ void mma16816(float* d, const uint32_t* a, const uint32_t* b) {
    asm volatile("mma.sync.aligned.m16n8k16.row.col.f32.f16.f16.f32 "
        "{%0,%1,%2,%3}, {%4,%5,%6,%7}, {%8,%9}, {%0,%1,%2,%3};"
        : "+f"(d[0]), "+f"(d[1]), "+f"(d[2]), "+f"(d[3])
        : "r"(a[0]), "r"(a[1]), "r"(a[2]), "r"(a[3]), "r"(b[0]), "r"(b[1]));
}
__device__ __forceinline__ void cpa16(uint32_t s, const void* g) {
    asm volatile("cp.async.cg.shared.global [%0], [%1], 16;" :: "r"(s), "l"(g));
}
#define CPA_COMMIT() asm volatile("cp.async.commit_group;" ::: "memory")
#define CPA_WAITG(k) asm volatile("cp.async.wait_group %0;" :: "n"(k) : "memory")

// ================= prep: X fp32 (original) -> fp16 (permuted, c fastest) ==========
__global__ __launch_bounds__(256) void prep_x(const float* __restrict__ X)
{
    __shared__ float ts[64][65];
    const int b = blockIdx.x >> 12, sblk = blockIdx.x & 4095;
    const size_t s0 = (size_t)sblk * 64;
    const int t = threadIdx.x, sl = t & 63, ch = t >> 6;
    const float* xp = X + (size_t)b * 64 * 262144 + s0;
    #pragma unroll
    for (int i = 0; i < 16; i++) {
        const int c = ch + i * 4;
        ts[sl][c] = xp[(size_t)c * 262144 + sl];
    }
    __syncthreads();
    const int srow = t >> 2, sub = t & 3;
    const size_t row = (size_t)b * 262144 + s0 + srow;
    __half* hp = g_xhi + row * 64 + sub * 16;
    #pragma unroll
    for (int j = 0; j < 16; j++)
        hp[j] = __float2half(ts[srow][sub * 16 + j]);
}

__global__ __launch_bounds__(256) void prep_w_all(
    const float* __restrict__ w_d, const float* __restrict__ w_h,
    const float* __restrict__ w_w, const float* __restrict__ w_pd,
    const float* __restrict__ w_ph, const float* __restrict__ w_pw)
{
    const int b = blockIdx.x;
    const float* W; int woff, n, row;
    if (b < 3072) {
        const int op = b >> 10; row = b & 1023; n = 1024; woff = op * 1048576;
        W = (op == 0) ? w_d : (op == 1) ? w_h : w_w;
    } else {
        const int t = b - 3072;
        const int op = t >> 8; row = t & 255; n = 256; woff = 3145728 + op * 65536;
        W = (op == 0) ? w_pd : (op == 1) ? w_ph : w_pw;
    }
    const float* wp = W + (size_t)row * n;
    __half* hp = g_whi + woff + (size_t)row * n;
    for (int c = threadIdx.x; c < n; c += 256)
        hp[c] = __float2half(wp[c]);
}

// ========== patch_fused: 3 patch ops, tile M=256 x N=64, K=768, writes g_acc ==========
__global__ __launch_bounds__(256, 2)
void patch_fused(const float* __restrict__ b_pd, const float* __restrict__ b_ph,
                 const float* __restrict__ b_pw)
{
    extern __shared__ __align__(16) char dsm[];
    __shared__ int base_in[256];
    __shared__ float bias_s[64];
    __shared__ int c0_s[3], step_s[3];
    __shared__ long wb_s[3];

    const int tid = threadIdx.x, lane = tid & 31, wid = tid >> 5;
    const int pqr = blockIdx.x, j2 = blockIdx.y;
    const int p = pqr >> 4, q = (pqr >> 2) & 3, r = pqr & 3;

    base_in[tid] = (tid >> 7) * 262144 + (j2 * 128 + (tid & 127)) * 64;
    if (tid < 64)
        bias_s[tid] = __ldg(b_pd + p * 64 + tid) + __ldg(b_ph + q * 64 + tid)
                    + __ldg(b_pw + r * 64 + tid);
    if (tid == 0) {
        c0_s[0] = q * 4 + r;      step_s[0] = 16;
        c0_s[1] = p * 16 + r;     step_s[1] = 4;
        c0_s[2] = p * 16 + q * 4; step_s[2] = 1;
        wb_s[0] = (long)(3145728 + p * 16384) * 2;
        wb_s[1] = (long)(3211264 + q * 16384) * 2;
        wb_s[2] = (long)(3276800 + r * 16384) * 2;
    }
    __syncthreads();

    const uint32_t sb = smem_u32(dsm);
    const int myrow = base_in[tid];
    const uint32_t aSm = (uint32_t)(tid * 80);
    const uint32_t bSm = (uint32_t)(PF_BOFF + (tid >> 2) * 80 + (tid & 3) * 16);
    const long bRow = (long)(tid >> 2) * 512 + (tid & 3) * 16;

    auto issue = [&](int ck) {
        const int op = ck >> 3, s32 = ck & 7, s = s32 >> 1, half = s32 & 1;
        const uint32_t st = sb + (uint32_t)((ck & 3) * PF_STG);
        const char* ga = (const char*)g_xhi
            + ((size_t)(myrow + c0_s[op] + s * step_s[op])) * 128 + half * 64;
        cpa16(st + aSm,      ga);
        cpa16(st + aSm + 16, ga + 16);
        cpa16(st + aSm + 32, ga + 32);
        cpa16(st + aSm + 48, ga + 48);
        const char* gb = (const char*)g_whi + wb_s[op] + bRow + s * 128 + half * 64;
        cpa16(st + bSm, gb);
    };

    const uint32_t a_lm = (uint32_t)((wid * 32 + (lane & 15)) * 80 + (lane >> 4) * 16);
    const uint32_t b_lm = (uint32_t)(PF_BOFF
        + (((lane >> 4) & 1) * 8 + (lane & 7)) * 80 + ((lane >> 3) & 1) * 16);

    float acc[2][8][4];
    #pragma unroll
    for (int i = 0; i < 2; i++)
        #pragma unroll
        for (int j = 0; j < 8; j++)
            #pragma unroll
            for (int u = 0; u < 4; u++) acc[i][j][u] = 0.f;

    issue(0); CPA_COMMIT();
    issue(1); CPA_COMMIT();
    issue(2); CPA_COMMIT();

    for (int ck = 0; ck < 24; ck++) {
        if (ck + 1 < 24) CPA_WAITG(2); else CPA_WAITG(0);
        __syncthreads();
        if (ck + 3 < 24) { issue(ck + 3); CPA_COMMIT(); }

        const uint32_t st = sb + (uint32_t)((ck & 3) * PF_STG);
        #pragma unroll
        for (int ks = 0; ks < 2; ks++) {
            const uint32_t ko = (uint32_t)(ks * 32);
            uint32_t ah[2][4], br[4];
            ldsm4(ah[0], st + a_lm + ko);
            ldsm4(ah[1], st + a_lm + 16 * 80 + ko);
            #pragma unroll
            for (int ntp = 0; ntp < 4; ntp++) {
                ldsm4(br, st + b_lm + ntp * 16 * 80 + ko);
                mma16816(acc[0][2*ntp],   ah[0], br);
                mma16816(acc[0][2*ntp+1], ah[0], br + 2);
                mma16816(acc[1][2*ntp],   ah[1], br);
                mma16816(acc[1][2*ntp+1], ah[1], br + 2);
            }
        }
    }

    {
        const int r0 = lane >> 2, cp = (lane & 3) * 2;
        #pragma unroll
        for (int mt = 0; mt < 2; mt++) {
            const int m0 = wid * 32 + mt * 16 + r0;
            const size_t o0 = ((size_t)(base_in[m0]     + pqr)) * 64;
            const size_t o1 = ((size_t)(base_in[m0 + 8] + pqr)) * 64;
            #pragma unroll
            for (int nt = 0; nt < 8; nt++) {
                const int c = nt * 8 + cp;
                const float bx = bias_s[c], by = bias_s[c + 1];
                *(float2*)(g_acc + o0 + c) = make_float2(acc[mt][nt][0] + bx,
                                                         acc[mt][nt][1] + by);
                *(float2*)(g_acc + o1 + c) = make_float2(acc[mt][nt][2] + bx,
                                                         acc[mt][nt][3] + by);
            }
        }
    }
}

// ======= shared image GEMM mainloop (128m x 128n, BK=64, 3-stage) =======
__device__ __forceinline__ void image_mainloop(
    const uint32_t sb, const int tid, const int* base_s,
    int woff, int str_sp, float acc[2][8][4])
{
    const int row = tid >> 1;
    const int half = (tid & 1) * 64;
    const int aBase = base_s[row];
    const char* aP = (const char*)g_xhi;
    const char* bP = (const char*)(g_whi + woff)
                   + ((size_t)(blockIdx.x * 128 + row)) * 2048 + half;
    const uint32_t rSm = (uint32_t)(row * APITCH + half);
    const int lane = tid & 31, wid = tid >> 5;
    const int wm = wid & 3, wn = wid >> 2;

    auto issue = [&](int ck) {
        const uint32_t st = sb + (uint32_t)((ck % 3) * STAGE_B);
        const size_t aoff = ((size_t)(aBase + ck * str_sp)) * 128 + half;
        cpa16(st + rSm,      aP + aoff);
        cpa16(st + rSm + 16, aP + aoff + 16);
        cpa16(st + rSm + 32, aP + aoff + 32);
        cpa16(st + rSm + 48, aP + aoff + 48);
        const size_t boff = (size_t)ck * 128;
        cpa16(st + B_OFF + rSm,      bP + boff);
        cpa16(st + B_OFF + rSm + 16, bP + boff + 16);
        cpa16(st + B_OFF + rSm + 32, bP + boff + 32);
        cpa16(st + B_OFF + rSm + 48, bP + boff + 48);
    };

    const uint32_t a_lm = (uint32_t)((wm * 32 + (lane & 15)) * APITCH + (lane >> 4) * 16);
    const uint32_t b_lm = (uint32_t)(B_OFF
        + (wn * 64 + ((lane >> 4) & 1) * 8 + (lane & 7)) * APITCH + ((lane >> 3) & 1) * 16);

    issue(0); CPA_COMMIT();
    issue(1); CPA_COMMIT();

    for (int ck = 0; ck < 16; ck++) {
        if (ck + 1 < 16) CPA_WAITG(1); else CPA_WAITG(0);
        __syncthreads();
        if (ck + 2 < 16) { issue(ck + 2); CPA_COMMIT(); }

        const uint32_t st = sb + (uint32_t)((ck % 3) * STAGE_B);
        #pragma unroll
        for (int ks = 0; ks < 4; ks++) {
            const uint32_t ko = (uint32_t)(ks * 32);
            uint32_t ah[2][4], br[4];
            ldsm4(ah[0], st + a_lm + ko);
            ldsm4(ah[1], st + a_lm + 16 * APITCH + ko);
            #pragma unroll
            for (int ntp = 0; ntp < 4; ntp++) {
                ldsm4(br, st + b_lm + ntp * 16 * APITCH + ko);
                mma16816(acc[0][2*ntp],   ah[0], br);
                mma16816(acc[0][2*ntp+1], ah[0], br + 2);
                mma16816(acc[1][2*ntp],   ah[1], br);
                mma16816(acc[1][2*ntp+1], ah[1], br + 2);
            }
        }
    }
}

// ==== image ops d (z=0) and h (z=1), RMW into g_acc ====
__global__ __launch_bounds__(256, 2)
void axial_dh(const float* __restrict__ b_d, const float* __restrict__ b_h)
{
    extern __shared__ __align__(16) char dsm[];
    __shared__ int base_s[128];

    const int tid = threadIdx.x;
    const int lane = tid & 31, wid = tid >> 5;
    const int nb = blockIdx.x, bx = blockIdx.y, op = blockIdx.z;
    const int wm = wid & 3, wn = wid >> 2;
    const int woff = op ? 1048576 : 0;
    const int str_sp = op ? 1024 : 16384;
    const float* Bias = op ? b_h : b_d;

    if (tid < 128) {
        const int m = bx * 128 + tid;
        base_s[tid] = op
            ? ((m & 1023) + ((m >> 10) & 15) * 16384 + (m >> 14) * 262144)
            : ((m & 16383) + (m >> 14) * 262144);
    }
    __syncthreads();

    float acc[2][8][4];
    #pragma unroll
    for (int i = 0; i < 2; i++)
        #pragma unroll
        for (int j = 0; j < 8; j++)
            #pragma unroll
            for (int q = 0; q < 4; q++) acc[i][j][q] = 0.f;

    image_mainloop(smem_u32(dsm), tid, base_s, woff, str_sp, acc);

    {
        const int s_out = nb * 2 + wn;
        const int r0 = lane >> 2, cp = (lane & 3) * 2;
        #pragma unroll
        for (int mt = 0; mt < 2; mt++) {
            const int ml = wm * 32 + mt * 16 + r0;
            const size_t row0 = (size_t)(base_s[ml]     + s_out * str_sp);
            const size_t row1 = (size_t)(base_s[ml + 8] + s_out * str_sp);
            #pragma unroll
            for (int nt = 0; nt < 8; nt++) {
                const int o = nb * 128 + wn * 64 + nt * 8 + cp;
                const int c_out = nt * 8 + cp;
                const float2 bv = __ldg((const float2*)(Bias + o));
                float2* g0 = (float2*)(g_acc + row0 * 64 + c_out);
                float2* g1 = (float2*)(g_acc + row1 * 64 + c_out);
                float2 v0 = *g0, v1 = *g1;
                v0.x += acc[mt][nt][0] + bv.x; v0.y += acc[mt][nt][1] + bv.y;
                v1.x += acc[mt][nt][2] + bv.x; v1.y += acc[mt][nt][3] + bv.y;
                *g0 = v0; *g1 = v1;
            }
        }
    }
}

// ==== image op w + final: reads g_acc, adds own result+bias, leaky+residual -> Y ====
__global__ __launch_bounds__(256, 2)
void image_w_final(const float* __restrict__ X, float* __restrict__ Y,
                   const float* __restrict__ b_w)
{
    extern __shared__ __align__(16) char dsm[];
    __shared__ int base_s[128];
    __shared__ float bias_s[128];

    const int tid = threadIdx.x;
    const int lane = tid & 31, wid = tid >> 5;
    const int nb = blockIdx.x, bx = blockIdx.y;
    const int wm = wid & 3, wn = wid >> 2;

    if (tid < 128) {
        const int m = bx * 128 + tid;
        base_s[tid] = (m & 63) + ((m >> 6) & 15) * 1024
                    + ((m >> 10) & 15) * 16384 + (m >> 14) * 262144;
        bias_s[tid] = __ldg(b_w + (nb * 2 + (tid >> 6)) * 64 + (tid & 63));
    }
    __syncthreads();

    float acc[2][8][4];
    #pragma unroll
    for (int i = 0; i < 2; i++)
        #pragma unroll
        for (int j = 0; j < 8; j++)
            #pragma unroll
            for (int q = 0; q < 4; q++) acc[i][j][q] = 0.f;

    image_mainloop(smem_u32(dsm), tid, base_s, 2097152, 64, acc);

    // stage: Cs[ml][wn*64+c] = acc + bias + g_acc
    float* Cs = (float*)dsm;
    __syncthreads();   // all warps done reading pipeline smem
    {
        const int r0 = lane >> 2, cp = (lane & 3) * 2;
        #pragma unroll
        for (int mt = 0; mt < 2; mt++) {
            const int ml = wm * 32 + mt * 16 + r0;
            const size_t row0 = (size_t)(base_s[ml]     + (nb * 2 + wn) * 64);
            const size_t row1 = (size_t)(base_s[ml + 8] + (nb * 2 + wn) * 64);
            #pragma unroll
            for (int nt = 0; nt < 8; nt++) {
                const int c = nt * 8 + cp;
                const float2 g0 = *(const float2*)(g_acc + row0 * 64 + c);
                const float2 g1 = *(const float2*)(g_acc + row1 * 64 + c);
                const float bxv = bias_s[wn * 64 + c], byv = bias_s[wn * 64 + c + 1];
                Cs[ml * CS_PITCH + wn * 64 + c]           = acc[mt][nt][0] + bxv + g0.x;
                Cs[ml * CS_PITCH + wn * 64 + c + 1]       = acc[mt][nt][1] + byv + g0.y;
                Cs[(ml + 8) * CS_PITCH + wn * 64 + c]     = acc[mt][nt][2] + bxv + g1.x;
                Cs[(ml + 8) * CS_PITCH + wn * 64 + c + 1] = acc[mt][nt][3] + byv + g1.y;
            }
        }
    }
    __syncthreads();

    // write pass: 256 runs of 64 floats (pqr contiguous), original layout
    const int h0 = (bx << 1) & 15, d_ = (bx >> 3) & 15, bb = bx >> 7;
    #pragma unroll 4
    for (int it = 0; it < 32; it++) {
        const int ri = it * 8 + wid;
        const int c = ri & 63, hh = (ri >> 6) & 1, wn2 = ri >> 7;
        const size_t off = (size_t)bb * 16777216 + (size_t)c * 262144
                         + d_ * 16384 + (h0 + hh) * 1024 + (nb * 2 + wn2) * 64;
        #pragma unroll
        for (int ps = 0; ps < 2; ps++) {
            const int pqr = ps * 32 + lane;
            float a = Cs[(hh * 64 + pqr) * CS_PITCH + wn2 * 64 + c];
            a = (a > 0.f ? a : 0.01f * a);
            Y[off + pqr] = X[off + pqr] + a;
        }
    }
}

extern "C" void kernel_launch(void* const* d_in, const int* in_sizes, int n_in,
                              void* d_out, int out_size)
{
    const float* x    = (const float*)d_in[0];
    const float* w_d  = (const float*)d_in[1];
    const float* b_d  = (const float*)d_in[2];
    const float* w_h  = (const float*)d_in[3];
    const float* b_h  = (const float*)d_in[4];
    const float* w_w  = (const float*)d_in[5];
    const float* b_w  = (const float*)d_in[6];
    const float* w_pd = (const float*)d_in[7];
    const float* b_pd = (const float*)d_in[8];
    const float* w_ph = (const float*)d_in[9];
    const float* b_ph = (const float*)d_in[10];
    const float* w_pw = (const float*)d_in[11];
    const float* b_pw = (const float*)d_in[12];

    cudaFuncSetAttribute(axial_dh,      cudaFuncAttributeMaxDynamicSharedMemorySize, DYN_SMEM);
    cudaFuncSetAttribute(image_w_final, cudaFuncAttributeMaxDynamicSharedMemorySize, DYN_SMEM);
    cudaFuncSetAttribute(patch_fused,   cudaFuncAttributeMaxDynamicSharedMemorySize, PF_DYN);

    prep_x<<<8192, 256>>>(x);
    prep_w_all<<<3840, 256>>>(w_d, w_h, w_w, w_pd, w_ph, w_pw);
    patch_fused<<<dim3(64, 32), 256, PF_DYN>>>(b_pd, b_ph, b_pw);
    axial_dh<<<dim3(8, 256, 2), 256, DYN_SMEM>>>(b_d, b_h);
    image_w_final<<<dim3(8, 256), 256, DYN_SMEM>>>(x, (float*)d_out, b_w);
}

// round 12
// speedup vs baseline: 1.1023x; 1.0022x over previous
#include <cuda_runtime.h>
#include <cuda_fp16.h>
#include <cstdint>

#define TOTAL_ELEMS 33554432

__device__ __align__(128) float g_acc[TOTAL_ELEMS];
__device__ __align__(128) __half g_xhi[TOTAL_ELEMS];
__device__ __align__(128) __half g_whi[3342336];

// ---- image GEMM stage: A 128x144B | B 128x144B (BK=64) ----
#define APITCH 144
#define B_OFF  18432
#define STAGE_B 36864
#define DYN_SMEM (3 * STAGE_B)      // 110592; 2 CTAs/SM

// ---- patch stage: A 256x80B | B 64x80B (BK=32), 4 stages = 102400 < DYN_SMEM ----
#define PF_BOFF 20480
#define PF_STG  25600

#define CS_PITCH 133                // fp32 staging pitch, conflict-free

__device__ __forceinline__ uint32_t smem_u32(const void* p) {
    uint32_t a;
    asm("{ .reg .u64 t; cvta.to.shared.u64 t, %1; cvt.u32.u64 %0, t; }" : "=r"(a) : "l"(p));
    return a;
}
__device__ __forceinline__ void ldsm4(uint32_t* r, uint32_t a) {
    asm volatile("ldmatrix.sync.aligned.m8n8.x4.shared.b16 {%0,%1,%2,%3}, [%4];"
        : "=r"(r[0]), "=r"(r[1]), "=r"(r[2]), "=r"(r[3]) : "r"(a));
}
__device__ __forceinline__ void mma16816(float* d, const uint32_t* a, const uint32_t* b) {
    asm volatile("mma.sync.aligned.m16n8k16.row.col.f32.f16.f16.f32 "
        "{%0,%1,%2,%3}, {%4,%5,%6,%7}, {%8,%9}, {%0,%1,%2,%3};"
        : "+f"(d[0]), "+f"(d[1]), "+f"(d[2]), "+f"(d[3])
        : "r"(a[0]), "r"(a[1]), "r"(a[2]), "r"(a[3]), "r"(b[0]), "r"(b[1]));
}
__device__ __forceinline__ void cpa16(uint32_t s, const void* g) {
    asm volatile("cp.async.cg.shared.global [%0], [%1], 16;" :: "r"(s), "l"(g));
}
__device__ __forceinline__ void red_add(float* p, float v) {
    asm volatile("red.global.add.f32 [%0], %1;" :: "l"(p), "f"(v) : "memory");
}
#define CPA_COMMIT() asm volatile("cp.async.commit_group;" ::: "memory")
#define CPA_WAITG(k) asm volatile("cp.async.wait_group %0;" :: "n"(k) : "memory")

// ========= prep_all: CTAs 0..8191 = X->fp16 permute + zero g_acc; 8192.. = W->fp16 =========
__global__ __launch_bounds__(256) void prep_all(
    const float* __restrict__ X,
    const float* __restrict__ w_d, const float* __restrict__ w_h,
    const float* __restrict__ w_w, const float* __restrict__ w_pd,
    const float* __restrict__ w_ph, const float* __restrict__ w_pw)
{
    const int t = threadIdx.x;
    if (blockIdx.x < 8192) {
        __shared__ float ts[64][65];
        const int b = blockIdx.x >> 12, sblk = blockIdx.x & 4095;
        const size_t s0 = (size_t)sblk * 64;
        const int sl = t & 63, ch = t >> 6;
        const float* xp = X + (size_t)b * 64 * 262144 + s0;
        #pragma unroll
        for (int i = 0; i < 16; i++) {
            const int c = ch + i * 4;
            ts[sl][c] = xp[(size_t)c * 262144 + sl];
        }
        // zero this CTA's g_acc region (64 rows x 64 c)
        {
            float4* gz = (float4*)(g_acc + ((size_t)b * 262144 + s0) * 64);
            const float4 z = make_float4(0.f, 0.f, 0.f, 0.f);
            #pragma unroll
            for (int i = 0; i < 4; i++) gz[t + i * 256] = z;
        }
        __syncthreads();
        const int srow = t >> 2, sub = t & 3;
        const size_t row = (size_t)b * 262144 + s0 + srow;
        __half* hp = g_xhi + row * 64 + sub * 16;
        #pragma unroll
        for (int j = 0; j < 16; j++)
            hp[j] = __float2half(ts[srow][sub * 16 + j]);
    } else {
        const int b = blockIdx.x - 8192;
        const float* W; int woff, n, row;
        if (b < 3072) {
            const int op = b >> 10; row = b & 1023; n = 1024; woff = op * 1048576;
            W = (op == 0) ? w_d : (op == 1) ? w_h : w_w;
        } else {
            const int u = b - 3072;
            const int op = u >> 8; row = u & 255; n = 256; woff = 3145728 + op * 65536;
            W = (op == 0) ? w_pd : (op == 1) ? w_ph : w_pw;
        }
        const float* wp = W + (size_t)row * n;
        __half* hp = g_whi + woff + (size_t)row * n;
        for (int c = t; c < n; c += 256)
            hp[c] = __float2half(wp[c]);
    }
}

// ===== acc_ops: one launch = image d (0..2047), image h (2048..4095), patch (4096..6143) =====
// All epilogues are red.global.add into zero-initialized g_acc -> race-free, order-free.
__global__ __launch_bounds__(256, 2)
void acc_ops(const float* __restrict__ b_d, const float* __restrict__ b_h,
             const float* __restrict__ b_pd, const float* __restrict__ b_ph,
             const float* __restrict__ b_pw)
{
    extern __shared__ __align__(16) char dsm[];
    __shared__ int base_sh[256];
    __shared__ float bias_sh[64];
    __shared__ int c0_s[3], step_s[3];
    __shared__ long wb_s[3];

    const int tid = threadIdx.x, lane = tid & 31, wid = tid >> 5;
    const uint32_t sb = smem_u32(dsm);
    const int bi = blockIdx.x;

    float acc[2][8][4];
    #pragma unroll
    for (int i = 0; i < 2; i++)
        #pragma unroll
        for (int j = 0; j < 8; j++)
            #pragma unroll
            for (int u = 0; u < 4; u++) acc[i][j][u] = 0.f;

    if (bi < 4096) {
        // ---------------- image op d (op=0) or h (op=1): 128m x 128n, BK=64, 3-stage ------
        const int op = bi >> 11, tt = bi & 2047;
        const int nb = tt & 7, bx = tt >> 3;
        const int wm = wid & 3, wn = wid >> 2;
        const int woff = op ? 1048576 : 0;
        const int str_sp = op ? 1024 : 16384;
        const float* Bias = op ? b_h : b_d;

        if (tid < 128) {
            const int m = bx * 128 + tid;
            base_sh[tid] = op
                ? ((m & 1023) + ((m >> 10) & 15) * 16384 + (m >> 14) * 262144)
                : ((m & 16383) + (m >> 14) * 262144);
        }
        __syncthreads();

        const int row = tid >> 1;
        const int half = (tid & 1) * 64;
        const int aBase = base_sh[row];
        const char* aP = (const char*)g_xhi;
        const char* bP = (const char*)(g_whi + woff) + ((size_t)(nb * 128 + row)) * 2048 + half;
        const uint32_t rSm = (uint32_t)(row * APITCH + half);

        auto issue = [&](int ck) {
            const uint32_t st = sb + (uint32_t)((ck % 3) * STAGE_B);
            const size_t aoff = ((size_t)(aBase + ck * str_sp)) * 128 + half;
            cpa16(st + rSm,      aP + aoff);
            cpa16(st + rSm + 16, aP + aoff + 16);
            cpa16(st + rSm + 32, aP + aoff + 32);
            cpa16(st + rSm + 48, aP + aoff + 48);
            const size_t boff = (size_t)ck * 128;
            cpa16(st + B_OFF + rSm,      bP + boff);
            cpa16(st + B_OFF + rSm + 16, bP + boff + 16);
            cpa16(st + B_OFF + rSm + 32, bP + boff + 32);
            cpa16(st + B_OFF + rSm + 48, bP + boff + 48);
        };

        const uint32_t a_lm = (uint32_t)((wm * 32 + (lane & 15)) * APITCH + (lane >> 4) * 16);
        const uint32_t b_lm = (uint32_t)(B_OFF
            + (wn * 64 + ((lane >> 4) & 1) * 8 + (lane & 7)) * APITCH + ((lane >> 3) & 1) * 16);

        issue(0); CPA_COMMIT();
        issue(1); CPA_COMMIT();

        for (int ck = 0; ck < 16; ck++) {
            if (ck + 1 < 16) CPA_WAITG(1); else CPA_WAITG(0);
            __syncthreads();
            if (ck + 2 < 16) { issue(ck + 2); CPA_COMMIT(); }

            const uint32_t st = sb + (uint32_t)((ck % 3) * STAGE_B);
            #pragma unroll
            for (int ks = 0; ks < 4; ks++) {
                const uint32_t ko = (uint32_t)(ks * 32);
                uint32_t ah[2][4], br[4];
                ldsm4(ah[0], st + a_lm + ko);
                ldsm4(ah[1], st + a_lm + 16 * APITCH + ko);
                #pragma unroll
                for (int ntp = 0; ntp < 4; ntp++) {
                    ldsm4(br, st + b_lm + ntp * 16 * APITCH + ko);
                    mma16816(acc[0][2*ntp],   ah[0], br);
                    mma16816(acc[0][2*ntp+1], ah[0], br + 2);
                    mma16816(acc[1][2*ntp],   ah[1], br);
                    mma16816(acc[1][2*ntp+1], ah[1], br + 2);
                }
            }
        }

        // epilogue: red.add into g_acc
        {
            const int s_out = nb * 2 + wn;
            const int r0 = lane >> 2, cp = (lane & 3) * 2;
            #pragma unroll
            for (int mt = 0; mt < 2; mt++) {
                const int ml = wm * 32 + mt * 16 + r0;
                const size_t row0 = (size_t)(base_sh[ml]     + s_out * str_sp);
                const size_t row1 = (size_t)(base_sh[ml + 8] + s_out * str_sp);
                #pragma unroll
                for (int nt = 0; nt < 8; nt++) {
                    const int o = nb * 128 + wn * 64 + nt * 8 + cp;
                    const int c = nt * 8 + cp;
                    const float2 bv = __ldg((const float2*)(Bias + o));
                    red_add(g_acc + row0 * 64 + c,     acc[mt][nt][0] + bv.x);
                    red_add(g_acc + row0 * 64 + c + 1, acc[mt][nt][1] + bv.y);
                    red_add(g_acc + row1 * 64 + c,     acc[mt][nt][2] + bv.x);
                    red_add(g_acc + row1 * 64 + c + 1, acc[mt][nt][3] + bv.y);
                }
            }
        }
    } else {
        // ---------------- patch: 3 ops fused, 256m x 64n, K=768, BK=32, 4-stage ----------
        const int tt = bi - 4096;
        const int pqr = tt & 63, j2 = tt >> 6;
        const int p = pqr >> 4, q = (pqr >> 2) & 3, r = pqr & 3;

        base_sh[tid] = (tid >> 7) * 262144 + (j2 * 128 + (tid & 127)) * 64;
        if (tid < 64)
            bias_sh[tid] = __ldg(b_pd + p * 64 + tid) + __ldg(b_ph + q * 64 + tid)
                         + __ldg(b_pw + r * 64 + tid);
        if (tid == 0) {
            c0_s[0] = q * 4 + r;      step_s[0] = 16;
            c0_s[1] = p * 16 + r;     step_s[1] = 4;
            c0_s[2] = p * 16 + q * 4; step_s[2] = 1;
            wb_s[0] = (long)(3145728 + p * 16384) * 2;
            wb_s[1] = (long)(3211264 + q * 16384) * 2;
            wb_s[2] = (long)(3276800 + r * 16384) * 2;
        }
        __syncthreads();

        const int myrow = base_sh[tid];
        const uint32_t aSm = (uint32_t)(tid * 80);
        const uint32_t bSm = (uint32_t)(PF_BOFF + (tid >> 2) * 80 + (tid & 3) * 16);
        const long bRow = (long)(tid >> 2) * 512 + (tid & 3) * 16;

        auto issue = [&](int ck) {
            const int op = ck >> 3, s32 = ck & 7, s = s32 >> 1, half = s32 & 1;
            const uint32_t st = sb + (uint32_t)((ck & 3) * PF_STG);
            const char* ga = (const char*)g_xhi
                + ((size_t)(myrow + c0_s[op] + s * step_s[op])) * 128 + half * 64;
            cpa16(st + aSm,      ga);
            cpa16(st + aSm + 16, ga + 16);
            cpa16(st + aSm + 32, ga + 32);
            cpa16(st + aSm + 48, ga + 48);
            const char* gb = (const char*)g_whi + wb_s[op] + bRow + s * 128 + half * 64;
            cpa16(st + bSm, gb);
        };

        const uint32_t a_lm = (uint32_t)((wid * 32 + (lane & 15)) * 80 + (lane >> 4) * 16);
        const uint32_t b_lm = (uint32_t)(PF_BOFF
            + (((lane >> 4) & 1) * 8 + (lane & 7)) * 80 + ((lane >> 3) & 1) * 16);

        issue(0); CPA_COMMIT();
        issue(1); CPA_COMMIT();
        issue(2); CPA_COMMIT();

        for (int ck = 0; ck < 24; ck++) {
            if (ck + 1 < 24) CPA_WAITG(2); else CPA_WAITG(0);
            __syncthreads();
            if (ck + 3 < 24) { issue(ck + 3); CPA_COMMIT(); }

            const uint32_t st = sb + (uint32_t)((ck & 3) * PF_STG);
            #pragma unroll
            for (int ks = 0; ks < 2; ks++) {
                const uint32_t ko = (uint32_t)(ks * 32);
                uint32_t ah[2][4], br[4];
                ldsm4(ah[0], st + a_lm + ko);
                ldsm4(ah[1], st + a_lm + 16 * 80 + ko);
                #pragma unroll
                for (int ntp = 0; ntp < 4; ntp++) {
                    ldsm4(br, st + b_lm + ntp * 16 * 80 + ko);
                    mma16816(acc[0][2*ntp],   ah[0], br);
                    mma16816(acc[0][2*ntp+1], ah[0], br + 2);
                    mma16816(acc[1][2*ntp],   ah[1], br);
                    mma16816(acc[1][2*ntp+1], ah[1], br + 2);
                }
            }
        }

        {
            const int r0 = lane >> 2, cp = (lane & 3) * 2;
            #pragma unroll
            for (int mt = 0; mt < 2; mt++) {
                const int m0 = wid * 32 + mt * 16 + r0;
                const size_t o0 = ((size_t)(base_sh[m0]     + pqr)) * 64;
                const size_t o1 = ((size_t)(base_sh[m0 + 8] + pqr)) * 64;
                #pragma unroll
                for (int nt = 0; nt < 8; nt++) {
                    const int c = nt * 8 + cp;
                    const float bx = bias_sh[c], by = bias_sh[c + 1];
                    red_add(g_acc + o0 + c,     acc[mt][nt][0] + bx);
                    red_add(g_acc + o0 + c + 1, acc[mt][nt][1] + by);
                    red_add(g_acc + o1 + c,     acc[mt][nt][2] + bx);
                    red_add(g_acc + o1 + c + 1, acc[mt][nt][3] + by);
                }
            }
        }
    }
}

// ==== image op w + final: reads g_acc, adds own result+bias, leaky+residual -> Y ====
__global__ __launch_bounds__(256, 2)
void image_w_final(const float* __restrict__ X, float* __restrict__ Y,
                   const float* __restrict__ b_w)
{
    extern __shared__ __align__(16) char dsm[];
    __shared__ int base_s[128];
    __shared__ float bias_s[128];

    const int tid = threadIdx.x;
    const int lane = tid & 31, wid = tid >> 5;
    const int nb = blockIdx.x, bx = blockIdx.y;
    const int wm = wid & 3, wn = wid >> 2;
    const uint32_t sb = smem_u32(dsm);

    if (tid < 128) {
        const int m = bx * 128 + tid;
        base_s[tid] = (m & 63) + ((m >> 6) & 15) * 1024
                    + ((m >> 10) & 15) * 16384 + (m >> 14) * 262144;
        bias_s[tid] = __ldg(b_w + (nb * 2 + (tid >> 6)) * 64 + (tid & 63));
    }
    __syncthreads();

    const int row = tid >> 1;
    const int half = (tid & 1) * 64;
    const int aBase = base_s[row];
    const char* aP = (const char*)g_xhi;
    const char* bP = (const char*)(g_whi + 2097152) + ((size_t)(nb * 128 + row)) * 2048 + half;
    const uint32_t rSm = (uint32_t)(row * APITCH + half);

    auto issue = [&](int ck) {
        const uint32_t st = sb + (uint32_t)((ck % 3) * STAGE_B);
        const size_t aoff = ((size_t)(aBase + ck * 64)) * 128 + half;
        cpa16(st + rSm,      aP + aoff);
        cpa16(st + rSm + 16, aP + aoff + 16);
        cpa16(st + rSm + 32, aP + aoff + 32);
        cpa16(st + rSm + 48, aP + aoff + 48);
        const size_t boff = (size_t)ck * 128;
        cpa16(st + B_OFF + rSm,      bP + boff);
        cpa16(st + B_OFF + rSm + 16, bP + boff + 16);
        cpa16(st + B_OFF + rSm + 32, bP + boff + 32);
        cpa16(st + B_OFF + rSm + 48, bP + boff + 48);
    };

    const uint32_t a_lm = (uint32_t)((wm * 32 + (lane & 15)) * APITCH + (lane >> 4) * 16);
    const uint32_t b_lm = (uint32_t)(B_OFF
        + (wn * 64 + ((lane >> 4) & 1) * 8 + (lane & 7)) * APITCH + ((lane >> 3) & 1) * 16);

    float acc[2][8][4];
    #pragma unroll
    for (int i = 0; i < 2; i++)
        #pragma unroll
        for (int j = 0; j < 8; j++)
            #pragma unroll
            for (int q = 0; q < 4; q++) acc[i][j][q] = 0.f;

    issue(0); CPA_COMMIT();
    issue(1); CPA_COMMIT();

    for (int ck = 0; ck < 16; ck++) {
        if (ck + 1 < 16) CPA_WAITG(1); else CPA_WAITG(0);
        __syncthreads();
        if (ck + 2 < 16) { issue(ck + 2); CPA_COMMIT(); }

        const uint32_t st = sb + (uint32_t)((ck % 3) * STAGE_B);
        #pragma unroll
        for (int ks = 0; ks < 4; ks++) {
            const uint32_t ko = (uint32_t)(ks * 32);
            uint32_t ah[2][4], br[4];
            ldsm4(ah[0], st + a_lm + ko);
            ldsm4(ah[1], st + a_lm + 16 * APITCH + ko);
            #pragma unroll
            for (int ntp = 0; ntp < 4; ntp++) {
                ldsm4(br, st + b_lm + ntp * 16 * APITCH + ko);
                mma16816(acc[0][2*ntp],   ah[0], br);
                mma16816(acc[0][2*ntp+1], ah[0], br + 2);
                mma16816(acc[1][2*ntp],   ah[1], br);
                mma16816(acc[1][2*ntp+1], ah[1], br + 2);
            }
        }
    }

    float* Cs = (float*)dsm;
    __syncthreads();
    {
        const int r0 = lane >> 2, cp = (lane & 3) * 2;
        #pragma unroll
        for (int mt = 0; mt < 2; mt++) {
            const int ml = wm * 32 + mt * 16 + r0;
            const size_t row0 = (size_t)(base_s[ml]     + (nb * 2 + wn) * 64);
            const size_t row1 = (size_t)(base_s[ml + 8] + (nb * 2 + wn) * 64);
            #pragma unroll
            for (int nt = 0; nt < 8; nt++) {
                const int c = nt * 8 + cp;
                const float2 g0 = *(const float2*)(g_acc + row0 * 64 + c);
                const float2 g1 = *(const float2*)(g_acc + row1 * 64 + c);
                const float bxv = bias_s[wn * 64 + c], byv = bias_s[wn * 64 + c + 1];
                Cs[ml * CS_PITCH + wn * 64 + c]           = acc[mt][nt][0] + bxv + g0.x;
                Cs[ml * CS_PITCH + wn * 64 + c + 1]       = acc[mt][nt][1] + byv + g0.y;
                Cs[(ml + 8) * CS_PITCH + wn * 64 + c]     = acc[mt][nt][2] + bxv + g1.x;
                Cs[(ml + 8) * CS_PITCH + wn * 64 + c + 1] = acc[mt][nt][3] + byv + g1.y;
            }
        }
    }
    __syncthreads();

    const int h0 = (bx << 1) & 15, d_ = (bx >> 3) & 15, bb = bx >> 7;
    #pragma unroll 4
    for (int it = 0; it < 32; it++) {
        const int ri = it * 8 + wid;
        const int c = ri & 63, hh = (ri >> 6) & 1, wn2 = ri >> 7;
        const size_t off = (size_t)bb * 16777216 + (size_t)c * 262144
                         + d_ * 16384 + (h0 + hh) * 1024 + (nb * 2 + wn2) * 64;
        #pragma unroll
        for (int ps = 0; ps < 2; ps++) {
            const int pqr = ps * 32 + lane;
            float a = Cs[(hh * 64 + pqr) * CS_PITCH + wn2 * 64 + c];
            a = (a > 0.f ? a : 0.01f * a);
            Y[off + pqr] = X[off + pqr] + a;
        }
    }
}

extern "C" void kernel_launch(void* const* d_in, const int* in_sizes, int n_in,
                              void* d_out, int out_size)
{
    const float* x    = (const float*)d_in[0];
    const float* w_d  = (const float*)d_in[1];
    const float* b_d  = (const float*)d_in[2];
    const float* w_h  = (const float*)d_in[3];
    const float* b_h  = (const float*)d_in[4];
    const float* w_w  = (const float*)d_in[5];
    const float* b_w  = (const float*)d_in[6];
    const float* w_pd = (const float*)d_in[7];
    const float* b_pd = (const float*)d_in[8];
    const float* w_ph = (const float*)d_in[9];
    const float* b_ph = (const float*)d_in[10];
    const float* w_pw = (const float*)d_in[11];
    const float* b_pw = (const float*)d_in[12];

    cudaFuncSetAttribute(acc_ops,       cudaFuncAttributeMaxDynamicSharedMemorySize, DYN_SMEM);
    cudaFuncSetAttribute(image_w_final, cudaFuncAttributeMaxDynamicSharedMemorySize, DYN_SMEM);

    prep_all<<<12032, 256>>>(x, w_d, w_h, w_w, w_pd, w_ph, w_pw);
    acc_ops<<<6144, 256, DYN_SMEM>>>(b_d, b_h, b_pd, b_ph, b_pw);
    image_w_final<<<dim3(8, 256), 256, DYN_SMEM>>>(x, (float*)d_out, b_w);
}

// round 13
// speedup vs baseline: 1.1306x; 1.0257x over previous
#include <cuda_runtime.h>
#include <cuda_fp16.h>
#include <cstdint>

#define TOTAL_ELEMS 33554432

__device__ __align__(128) float g_acc[TOTAL_ELEMS];
__device__ __align__(128) __half g_xhi[TOTAL_ELEMS];
__device__ __align__(128) __half g_whi[3342336];

// ---- image GEMM stage: A 128x144B | B 128x144B (BK=64) ----
#define APITCH 144
#define B_OFF  18432
#define STAGE_B 36864
#define DYN_SMEM (3 * STAGE_B)      // 110592; 2 CTAs/SM

// ---- patch stage: A 256x80B | B 64x80B (BK=32), 4 stages ----
#define PF_BOFF 20480
#define PF_STG  25600
#define PF_DYN  (4 * PF_STG)        // 102400; 2 CTAs/SM

#define CS_PITCH 133

__device__ __forceinline__ uint32_t smem_u32(const void* p) {
    uint32_t a;
    asm("{ .reg .u64 t; cvta.to.shared.u64 t, %1; cvt.u32.u64 %0, t; }" : "=r"(a) : "l"(p));
    return a;
}
__device__ __forceinline__ void ldsm4(uint32_t* r, uint32_t a) {
    asm volatile("ldmatrix.sync.aligned.m8n8.x4.shared.b16 {%0,%1,%2,%3}, [%4];"
        : "=r"(r[0]), "=r"(r[1]), "=r"(r[2]), "=r"(r[3]) : "r"(a));
}
__device__ __forceinline__ void mma16816(float* d, const uint32_t* a, const uint32_t* b) {
    asm volatile("mma.sync.aligned.m16n8k16.row.col.f32.f16.f16.f32 "
        "{%0,%1,%2,%3}, {%4,%5,%6,%7}, {%8,%9}, {%0,%1,%2,%3};"
        : "+f"(d[0]), "+f"(d[1]), "+f"(d[2]), "+f"(d[3])
        : "r"(a[0]), "r"(a[1]), "r"(a[2]), "r"(a[3]), "r"(b[0]), "r"(b[1]));
}
__device__ __forceinline__ void cpa16(uint32_t s, const void* g) {
    asm volatile("cp.async.cg.shared.global [%0], [%1], 16;" :: "r"(s), "l"(g));
}
__device__ __forceinline__ void red_add(float* p, float v) {
    asm volatile("red.global.add.f32 [%0], %1;" :: "l"(p), "f"(v) : "memory");
}
#define CPA_COMMIT() asm volatile("cp.async.commit_group;" ::: "memory")
#define CPA_WAITG(k) asm volatile("cp.async.wait_group %0;" :: "n"(k) : "memory")

// ========= prep_all: CTAs 0..8191 = X->fp16 permute; 8192.. = W->fp16 (no zeroing) =========
__global__ __launch_bounds__(256) void prep_all(
    const float* __restrict__ X,
    const float* __restrict__ w_d, const float* __restrict__ w_h,
    const float* __restrict__ w_w, const float* __restrict__ w_pd,
    const float* __restrict__ w_ph, const float* __restrict__ w_pw)
{
    const int t = threadIdx.x;
    if (blockIdx.x < 8192) {
        __shared__ float ts[64][65];
        const int b = blockIdx.x >> 12, sblk = blockIdx.x & 4095;
        const size_t s0 = (size_t)sblk * 64;
        const int sl = t & 63, ch = t >> 6;
        const float* xp = X + (size_t)b * 64 * 262144 + s0;
        #pragma unroll
        for (int i = 0; i < 16; i++) {
            const int c = ch + i * 4;
            ts[sl][c] = xp[(size_t)c * 262144 + sl];
        }
        __syncthreads();
        const int srow = t >> 2, sub = t & 3;
        const size_t row = (size_t)b * 262144 + s0 + srow;
        __half* hp = g_xhi + row * 64 + sub * 16;
        #pragma unroll
        for (int j = 0; j < 16; j++)
            hp[j] = __float2half(ts[srow][sub * 16 + j]);
    } else {
        const int b = blockIdx.x - 8192;
        const float* W; int woff, n, row;
        if (b < 3072) {
            const int op = b >> 10; row = b & 1023; n = 1024; woff = op * 1048576;
            W = (op == 0) ? w_d : (op == 1) ? w_h : w_w;
        } else {
            const int u = b - 3072;
            const int op = u >> 8; row = u & 255; n = 256; woff = 3145728 + op * 65536;
            W = (op == 0) ? w_pd : (op == 1) ? w_ph : w_pw;
        }
        const float* wp = W + (size_t)row * n;
        __half* hp = g_whi + woff + (size_t)row * n;
        for (int c = t; c < n; c += 256)
            hp[c] = __float2half(wp[c]);
    }
}

// ========== patch_fused: 3 patch ops, 256m x 64n, K=768, plain stores to g_acc ==========
__global__ __launch_bounds__(256, 2)
void patch_fused(const float* __restrict__ b_pd, const float* __restrict__ b_ph,
                 const float* __restrict__ b_pw)
{
    extern __shared__ __align__(16) char dsm[];
    __shared__ int base_sh[256];
    __shared__ float bias_sh[64];
    __shared__ int c0_s[3], step_s[3];
    __shared__ long wb_s[3];

    const int tid = threadIdx.x, lane = tid & 31, wid = tid >> 5;
    const int pqr = blockIdx.x, j2 = blockIdx.y;
    const int p = pqr >> 4, q = (pqr >> 2) & 3, r = pqr & 3;

    base_sh[tid] = (tid >> 7) * 262144 + (j2 * 128 + (tid & 127)) * 64;
    if (tid < 64)
        bias_sh[tid] = __ldg(b_pd + p * 64 + tid) + __ldg(b_ph + q * 64 + tid)
                     + __ldg(b_pw + r * 64 + tid);
    if (tid == 0) {
        c0_s[0] = q * 4 + r;      step_s[0] = 16;
        c0_s[1] = p * 16 + r;     step_s[1] = 4;
        c0_s[2] = p * 16 + q * 4; step_s[2] = 1;
        wb_s[0] = (long)(3145728 + p * 16384) * 2;
        wb_s[1] = (long)(3211264 + q * 16384) * 2;
        wb_s[2] = (long)(3276800 + r * 16384) * 2;
    }
    __syncthreads();

    const uint32_t sb = smem_u32(dsm);
    const int myrow = base_sh[tid];
    const uint32_t aSm = (uint32_t)(tid * 80);
    const uint32_t bSm = (uint32_t)(PF_BOFF + (tid >> 2) * 80 + (tid & 3) * 16);
    const long bRow = (long)(tid >> 2) * 512 + (tid & 3) * 16;

    auto issue = [&](int ck) {
        const int op = ck >> 3, s32 = ck & 7, s = s32 >> 1, half = s32 & 1;
        const uint32_t st = sb + (uint32_t)((ck & 3) * PF_STG);
        const char* ga = (const char*)g_xhi
            + ((size_t)(myrow + c0_s[op] + s * step_s[op])) * 128 + half * 64;
        cpa16(st + aSm,      ga);
        cpa16(st + aSm + 16, ga + 16);
        cpa16(st + aSm + 32, ga + 32);
        cpa16(st + aSm + 48, ga + 48);
        const char* gb = (const char*)g_whi + wb_s[op] + bRow + s * 128 + half * 64;
        cpa16(st + bSm, gb);
    };

    const uint32_t a_lm = (uint32_t)((wid * 32 + (lane & 15)) * 80 + (lane >> 4) * 16);
    const uint32_t b_lm = (uint32_t)(PF_BOFF
        + (((lane >> 4) & 1) * 8 + (lane & 7)) * 80 + ((lane >> 3) & 1) * 16);

    float acc[2][8][4];
    #pragma unroll
    for (int i = 0; i < 2; i++)
        #pragma unroll
        for (int j = 0; j < 8; j++)
            #pragma unroll
            for (int u = 0; u < 4; u++) acc[i][j][u] = 0.f;

    issue(0); CPA_COMMIT();
    issue(1); CPA_COMMIT();
    issue(2); CPA_COMMIT();

    for (int ck = 0; ck < 24; ck++) {
        if (ck + 1 < 24) CPA_WAITG(2); else CPA_WAITG(0);
        __syncthreads();
        if (ck + 3 < 24) { issue(ck + 3); CPA_COMMIT(); }

        const uint32_t st = sb + (uint32_t)((ck & 3) * PF_STG);
        #pragma unroll
        for (int ks = 0; ks < 2; ks++) {
            const uint32_t ko = (uint32_t)(ks * 32);
            uint32_t ah[2][4], br[4];
            ldsm4(ah[0], st + a_lm + ko);
            ldsm4(ah[1], st + a_lm + 16 * 80 + ko);
            #pragma unroll
            for (int ntp = 0; ntp < 4; ntp++) {
                ldsm4(br, st + b_lm + ntp * 16 * 80 + ko);
                mma16816(acc[0][2*ntp],   ah[0], br);
                mma16816(acc[0][2*ntp+1], ah[0], br + 2);
                mma16816(acc[1][2*ntp],   ah[1], br);
                mma16816(acc[1][2*ntp+1], ah[1], br + 2);
            }
        }
    }

    {
        const int r0 = lane >> 2, cp = (lane & 3) * 2;
        #pragma unroll
        for (int mt = 0; mt < 2; mt++) {
            const int m0 = wid * 32 + mt * 16 + r0;
            const size_t o0 = ((size_t)(base_sh[m0]     + pqr)) * 64;
            const size_t o1 = ((size_t)(base_sh[m0 + 8] + pqr)) * 64;
            #pragma unroll
            for (int nt = 0; nt < 8; nt++) {
                const int c = nt * 8 + cp;
                const float bx = bias_sh[c], by = bias_sh[c + 1];
                *(float2*)(g_acc + o0 + c) = make_float2(acc[mt][nt][0] + bx,
                                                         acc[mt][nt][1] + by);
                *(float2*)(g_acc + o1 + c) = make_float2(acc[mt][nt][2] + bx,
                                                         acc[mt][nt][3] + by);
            }
        }
    }
}

// ===== images d (0..2047) + h (2048..4095): 128m x 128n BK=64, red.add epilogue =====
__global__ __launch_bounds__(256, 2)
void images_dh(const float* __restrict__ b_d, const float* __restrict__ b_h)
{
    extern __shared__ __align__(16) char dsm[];
    __shared__ int base_sh[128];

    const int tid = threadIdx.x, lane = tid & 31, wid = tid >> 5;
    const uint32_t sb = smem_u32(dsm);
    const int bi = blockIdx.x;
    const int op = bi >> 11, tt = bi & 2047;
    const int nb = tt & 7, bx = tt >> 3;
    const int wm = wid & 3, wn = wid >> 2;
    const int woff = op ? 1048576 : 0;
    const int str_sp = op ? 1024 : 16384;
    const float* Bias = op ? b_h : b_d;

    if (tid < 128) {
        const int m = bx * 128 + tid;
        base_sh[tid] = op
            ? ((m & 1023) + ((m >> 10) & 15) * 16384 + (m >> 14) * 262144)
            : ((m & 16383) + (m >> 14) * 262144);
    }
    __syncthreads();

    const int row = tid >> 1;
    const int half = (tid & 1) * 64;
    const int aBase = base_sh[row];
    const char* aP = (const char*)g_xhi;
    const char* bP = (const char*)(g_whi + woff) + ((size_t)(nb * 128 + row)) * 2048 + half;
    const uint32_t rSm = (uint32_t)(row * APITCH + half);

    auto issue = [&](int ck) {
        const uint32_t st = sb + (uint32_t)((ck % 3) * STAGE_B);
        const size_t aoff = ((size_t)(aBase + ck * str_sp)) * 128 + half;
        cpa16(st + rSm,      aP + aoff);
        cpa16(st + rSm + 16, aP + aoff + 16);
        cpa16(st + rSm + 32, aP + aoff + 32);
        cpa16(st + rSm + 48, aP + aoff + 48);
        const size_t boff = (size_t)ck * 128;
        cpa16(st + B_OFF + rSm,      bP + boff);
        cpa16(st + B_OFF + rSm + 16, bP + boff + 16);
        cpa16(st + B_OFF + rSm + 32, bP + boff + 32);
        cpa16(st + B_OFF + rSm + 48, bP + boff + 48);
    };

    const uint32_t a_lm = (uint32_t)((wm * 32 + (lane & 15)) * APITCH + (lane >> 4) * 16);
    const uint32_t b_lm = (uint32_t)(B_OFF
        + (wn * 64 + ((lane >> 4) & 1) * 8 + (lane & 7)) * APITCH + ((lane >> 3) & 1) * 16);

    float acc[2][8][4];
    #pragma unroll
    for (int i = 0; i < 2; i++)
        #pragma unroll
        for (int j = 0; j < 8; j++)
            #pragma unroll
            for (int q = 0; q < 4; q++) acc[i][j][q] = 0.f;

    issue(0); CPA_COMMIT();
    issue(1); CPA_COMMIT();

    for (int ck = 0; ck < 16; ck++) {
        if (ck + 1 < 16) CPA_WAITG(1); else CPA_WAITG(0);
        __syncthreads();
        if (ck + 2 < 16) { issue(ck + 2); CPA_COMMIT(); }

        const uint32_t st = sb + (uint32_t)((ck % 3) * STAGE_B);
        #pragma unroll
        for (int ks = 0; ks < 4; ks++) {
            const uint32_t ko = (uint32_t)(ks * 32);
            uint32_t ah[2][4], br[4];
            ldsm4(ah[0], st + a_lm + ko);
            ldsm4(ah[1], st + a_lm + 16 * APITCH + ko);
            #pragma unroll
            for (int ntp = 0; ntp < 4; ntp++) {
                ldsm4(br, st + b_lm + ntp * 16 * APITCH + ko);
                mma16816(acc[0][2*ntp],   ah[0], br);
                mma16816(acc[0][2*ntp+1], ah[0], br + 2);
                mma16816(acc[1][2*ntp],   ah[1], br);
                mma16816(acc[1][2*ntp+1], ah[1], br + 2);
            }
        }
    }

    {
        const int s_out = nb * 2 + wn;
        const int r0 = lane >> 2, cp = (lane & 3) * 2;
        #pragma unroll
        for (int mt = 0; mt < 2; mt++) {
            const int ml = wm * 32 + mt * 16 + r0;
            const size_t row0 = (size_t)(base_sh[ml]     + s_out * str_sp);
            const size_t row1 = (size_t)(base_sh[ml + 8] + s_out * str_sp);
            #pragma unroll
            for (int nt = 0; nt < 8; nt++) {
                const int o = nb * 128 + wn * 64 + nt * 8 + cp;
                const int c = nt * 8 + cp;
                const float2 bv = __ldg((const float2*)(Bias + o));
                red_add(g_acc + row0 * 64 + c,     acc[mt][nt][0] + bv.x);
                red_add(g_acc + row0 * 64 + c + 1, acc[mt][nt][1] + bv.y);
                red_add(g_acc + row1 * 64 + c,     acc[mt][nt][2] + bv.x);
                red_add(g_acc + row1 * 64 + c + 1, acc[mt][nt][3] + bv.y);
            }
        }
    }
}

// ==== image op w + final: reads g_acc, adds own result+bias, leaky+residual -> Y ====
__global__ __launch_bounds__(256, 2)
void image_w_final(const float* __restrict__ X, float* __restrict__ Y,
                   const float* __restrict__ b_w)
{
    extern __shared__ __align__(16) char dsm[];
    __shared__ int base_s[128];
    __shared__ float bias_s[128];

    const int tid = threadIdx.x;
    const int lane = tid & 31, wid = tid >> 5;
    const int nb = blockIdx.x, bx = blockIdx.y;
    const int wm = wid & 3, wn = wid >> 2;
    const uint32_t sb = smem_u32(dsm);

    if (tid < 128) {
        const int m = bx * 128 + tid;
        base_s[tid] = (m & 63) + ((m >> 6) & 15) * 1024
                    + ((m >> 10) & 15) * 16384 + (m >> 14) * 262144;
        bias_s[tid] = __ldg(b_w + (nb * 2 + (tid >> 6)) * 64 + (tid & 63));
    }
    __syncthreads();

    const int row = tid >> 1;
    const int half = (tid & 1) * 64;
    const int aBase = base_s[row];
    const char* aP = (const char*)g_xhi;
    const char* bP = (const char*)(g_whi + 2097152) + ((size_t)(nb * 128 + row)) * 2048 + half;
    const uint32_t rSm = (uint32_t)(row * APITCH + half);

    auto issue = [&](int ck) {
        const uint32_t st = sb + (uint32_t)((ck % 3) * STAGE_B);
        const size_t aoff = ((size_t)(aBase + ck * 64)) * 128 + half;
        cpa16(st + rSm,      aP + aoff);
        cpa16(st + rSm + 16, aP + aoff + 16);
        cpa16(st + rSm + 32, aP + aoff + 32);
        cpa16(st + rSm + 48, aP + aoff + 48);
        const size_t boff = (size_t)ck * 128;
        cpa16(st + B_OFF + rSm,      bP + boff);
        cpa16(st + B_OFF + rSm + 16, bP + boff + 16);
        cpa16(st + B_OFF + rSm + 32, bP + boff + 32);
        cpa16(st + B_OFF + rSm + 48, bP + boff + 48);
    };

    const uint32_t a_lm = (uint32_t)((wm * 32 + (lane & 15)) * APITCH + (lane >> 4) * 16);
    const uint32_t b_lm = (uint32_t)(B_OFF
        + (wn * 64 + ((lane >> 4) & 1) * 8 + (lane & 7)) * APITCH + ((lane >> 3) & 1) * 16);

    float acc[2][8][4];
    #pragma unroll
    for (int i = 0; i < 2; i++)
        #pragma unroll
        for (int j = 0; j < 8; j++)
            #pragma unroll
            for (int q = 0; q < 4; q++) acc[i][j][q] = 0.f;

    issue(0); CPA_COMMIT();
    issue(1); CPA_COMMIT();

    for (int ck = 0; ck < 16; ck++) {
        if (ck + 1 < 16) CPA_WAITG(1); else CPA_WAITG(0);
        __syncthreads();
        if (ck + 2 < 16) { issue(ck + 2); CPA_COMMIT(); }

        const uint32_t st = sb + (uint32_t)((ck % 3) * STAGE_B);
        #pragma unroll
        for (int ks = 0; ks < 4; ks++) {
            const uint32_t ko = (uint32_t)(ks * 32);
            uint32_t ah[2][4], br[4];
            ldsm4(ah[0], st + a_lm + ko);
            ldsm4(ah[1], st + a_lm + 16 * APITCH + ko);
            #pragma unroll
            for (int ntp = 0; ntp < 4; ntp++) {
                ldsm4(br, st + b_lm + ntp * 16 * APITCH + ko);
                mma16816(acc[0][2*ntp],   ah[0], br);
                mma16816(acc[0][2*ntp+1], ah[0], br + 2);
                mma16816(acc[1][2*ntp],   ah[1], br);
                mma16816(acc[1][2*ntp+1], ah[1], br + 2);
            }
        }
    }

    float* Cs = (float*)dsm;
    __syncthreads();
    {
        const int r0 = lane >> 2, cp = (lane & 3) * 2;
        #pragma unroll
        for (int mt = 0; mt < 2; mt++) {
            const int ml = wm * 32 + mt * 16 + r0;
            const size_t row0 = (size_t)(base_s[ml]     + (nb * 2 + wn) * 64);
            const size_t row1 = (size_t)(base_s[ml + 8] + (nb * 2 + wn) * 64);
            #pragma unroll
            for (int nt = 0; nt < 8; nt++) {
                const int c = nt * 8 + cp;
                const float2 g0 = *(const float2*)(g_acc + row0 * 64 + c);
                const float2 g1 = *(const float2*)(g_acc + row1 * 64 + c);
                const float bxv = bias_s[wn * 64 + c], byv = bias_s[wn * 64 + c + 1];
                Cs[ml * CS_PITCH + wn * 64 + c]           = acc[mt][nt][0] + bxv + g0.x;
                Cs[ml * CS_PITCH + wn * 64 + c + 1]       = acc[mt][nt][1] + byv + g0.y;
                Cs[(ml + 8) * CS_PITCH + wn * 64 + c]     = acc[mt][nt][2] + bxv + g1.x;
                Cs[(ml + 8) * CS_PITCH + wn * 64 + c + 1] = acc[mt][nt][3] + byv + g1.y;
            }
        }
    }
    __syncthreads();

    const int h0 = (bx << 1) & 15, d_ = (bx >> 3) & 15, bb = bx >> 7;
    #pragma unroll 4
    for (int it = 0; it < 32; it++) {
        const int ri = it * 8 + wid;
        const int c = ri & 63, hh = (ri >> 6) & 1, wn2 = ri >> 7;
        const size_t off = (size_t)bb * 16777216 + (size_t)c * 262144
                         + d_ * 16384 + (h0 + hh) * 1024 + (nb * 2 + wn2) * 64;
        #pragma unroll
        for (int ps = 0; ps < 2; ps++) {
            const int pqr = ps * 32 + lane;
            float a = Cs[(hh * 64 + pqr) * CS_PITCH + wn2 * 64 + c];
            a = (a > 0.f ? a : 0.01f * a);
            Y[off + pqr] = X[off + pqr] + a;
        }
    }
}

extern "C" void kernel_launch(void* const* d_in, const int* in_sizes, int n_in,
                              void* d_out, int out_size)
{
    const float* x    = (const float*)d_in[0];
    const float* w_d  = (const float*)d_in[1];
    const float* b_d  = (const float*)d_in[2];
    const float* w_h  = (const float*)d_in[3];
    const float* b_h  = (const float*)d_in[4];
    const float* w_w  = (const float*)d_in[5];
    const float* b_w  = (const float*)d_in[6];
    const float* w_pd = (const float*)d_in[7];
    const float* b_pd = (const float*)d_in[8];
    const float* w_ph = (const float*)d_in[9];
    const float* b_ph = (const float*)d_in[10];
    const float* w_pw = (const float*)d_in[11];
    const float* b_pw = (const float*)d_in[12];

    cudaFuncSetAttribute(patch_fused,   cudaFuncAttributeMaxDynamicSharedMemorySize, PF_DYN);
    cudaFuncSetAttribute(images_dh,     cudaFuncAttributeMaxDynamicSharedMemorySize, DYN_SMEM);
    cudaFuncSetAttribute(image_w_final, cudaFuncAttributeMaxDynamicSharedMemorySize, DYN_SMEM);

    prep_all<<<12032, 256>>>(x, w_d, w_h, w_w, w_pd, w_ph, w_pw);
    patch_fused<<<dim3(64, 32), 256, PF_DYN>>>(b_pd, b_ph, b_pw);
    images_dh<<<4096, 256, DYN_SMEM>>>(b_d, b_h);
    image_w_final<<<dim3(8, 256), 256, DYN_SMEM>>>(x, (float*)d_out, b_w);
}